// round 1
// baseline (speedup 1.0000x reference)
#include <cuda_runtime.h>

#define OUT_N 224
#define H 512
#define W 512
#define HW (H*W)

__global__ __launch_bounds__(OUT_N)
void velhist_kernel(const float* __restrict__ flows,
                    const float* __restrict__ boxes,
                    float* __restrict__ out)
{
    __shared__ float s_wy0[OUT_N], s_wy1[OUT_N];
    __shared__ int   s_r0[OUT_N],  s_r1[OUT_N];
    __shared__ float s_red[7][16];

    const int m = blockIdx.x;
    const int j = threadIdx.x;

    const float fb = boxes[m*5+0];
    const float bx1 = boxes[m*5+1];
    const float by1 = boxes[m*5+2];
    const float bx2 = boxes[m*5+3];
    const float by2 = boxes[m*5+4];
    const int b = (int)fb;
    const float roi_w = fmaxf(bx2 - bx1, 1.0f);
    const float roi_h = fmaxf(by2 - by1, 1.0f);

    // Per-thread column setup (hoisted out of the row loop entirely)
    const float gx = ((float)j + 0.5f) / (float)OUT_N;
    const float px = bx1 + gx * roi_w;
    const bool vx = (px >= -1.0f) && (px <= (float)W);
    const float pxc = fminf(fmaxf(px, 0.0f), (float)(W - 1));
    const float x0f = floorf(pxc);
    const int x0 = (int)x0f;
    const int x1i = min(x0 + 1, W - 1);
    const float fx = pxc - x0f;
    const float wx0 = vx ? (1.0f - fx) : 0.0f;  // masking folded into weights
    const float wx1 = vx ? fx : 0.0f;

    // Per-row setup: row i computed by thread i, shared across the block
    {
        const int i = j;
        const float gy = ((float)i + 0.5f) / (float)OUT_N;
        const float py = by1 + gy * roi_h;
        const bool vy = (py >= -1.0f) && (py <= (float)H);
        const float pyc = fminf(fmaxf(py, 0.0f), (float)(H - 1));
        const float y0f = floorf(pyc);
        const int y0 = (int)y0f;
        const int y1r = min(y0 + 1, H - 1);
        const float fy = pyc - y0f;
        s_wy0[i] = vy ? (1.0f - fy) : 0.0f;
        s_wy1[i] = vy ? fy : 0.0f;
        s_r0[i] = y0 * W;
        s_r1[i] = y1r * W;
    }
    __syncthreads();

    const float* __restrict__ pu = flows + (size_t)b * (2 * HW);
    const float* __restrict__ pv = pu + HW;

    float sums[8];
#pragma unroll
    for (int k = 0; k < 8; ++k) sums[k] = 0.0f;
    unsigned long long cnt = 0ULL;   // 8 packed byte counters (max 224 each)

#pragma unroll 2
    for (int i = 0; i < OUT_N; ++i) {
        const int r0 = s_r0[i];
        const int r1 = s_r1[i];
        const float wy0 = s_wy0[i];
        const float wy1 = s_wy1[i];
        const float w00 = wy0 * wx0, w01 = wy0 * wx1;
        const float w10 = wy1 * wx0, w11 = wy1 * wx1;

        const float u = pu[r0 + x0] * w00 + pu[r0 + x1i] * w01
                      + pu[r1 + x0] * w10 + pu[r1 + x1i] * w11;
        const float v = pv[r0 + x0] * w00 + pv[r0 + x1i] * w01
                      + pv[r1 + x0] * w10 + pv[r1 + x1i] * w11;

        const float sq = u * u + v * v;
        const float mag = (sq > 0.0f) ? (sq * rsqrtf(sq)) : 0.0f;

        // bin = floor((atan2(u,v)+pi) * 8/(2pi)) clipped — boundaries are the
        // lines u=0, v=0, u=+-v, so a comparison tree is exact (no atan2).
        int bin;
        if (u < 0.0f) {
            if (v < 0.0f) bin = (u > v)  ? 0 : 1;   // theta in (-pi, -pi/2)
            else          bin = (u < -v) ? 2 : 3;   // theta in (-pi/2, 0)
        } else {
            if (v < 0.0f) bin = (u > -v) ? 6 : 7;   // theta in (pi/2, pi)
            else          bin = (u < v)  ? 4 : 5;   // theta in (0, pi/2)
        }
        if (sq == 0.0f) bin = 4;  // atan2(0,0)=0 -> bin 4 (masked samples too)

#pragma unroll
        for (int k = 0; k < 8; ++k) sums[k] += (bin == k) ? mag : 0.0f;
        cnt += 1ULL << (bin << 3);
    }

    // Unpack byte counters to floats
    float cf[8];
#pragma unroll
    for (int k = 0; k < 8; ++k)
        cf[k] = (float)((unsigned)(cnt >> (k << 3)) & 0xFFu);

    // Warp-level reduction (all 7 warps are full: 224 threads)
#pragma unroll
    for (int off = 16; off > 0; off >>= 1) {
#pragma unroll
        for (int k = 0; k < 8; ++k) {
            sums[k] += __shfl_down_sync(0xFFFFFFFFu, sums[k], off);
            cf[k]   += __shfl_down_sync(0xFFFFFFFFu, cf[k], off);
        }
    }
    const int warp = j >> 5, lane = j & 31;
    if (lane == 0) {
#pragma unroll
        for (int k = 0; k < 8; ++k) {
            s_red[warp][k]     = sums[k];
            s_red[warp][8 + k] = cf[k];
        }
    }
    __syncthreads();
    if (j < 8) {
        float S = 0.0f, C = 0.0f;
#pragma unroll
        for (int w = 0; w < 7; ++w) { S += s_red[w][j]; C += s_red[w][8 + j]; }
        out[m * 8 + j] = (C != 0.0f) ? (S / C) : 0.0f;
    }
}

extern "C" void kernel_launch(void* const* d_in, const int* in_sizes, int n_in,
                              void* d_out, int out_size)
{
    const float* flows = (const float*)d_in[0];
    const float* boxes = (const float*)d_in[1];
    float* out = (float*)d_out;
    const int M = in_sizes[1] / 5;   // boxes are (M, 5)
    velhist_kernel<<<M, OUT_N>>>(flows, boxes, out);
}

// round 2
// speedup vs baseline: 1.2306x; 1.2306x over previous
#include <cuda_runtime.h>

#define OUT_N 224
#define H 512
#define W 512
#define HW (H*W)
#define SPLIT 2
#define ROWS_PER (OUT_N / SPLIT)   // 112
#define MAX_M 512

// Per-(box, half) partials: 8 sums + 8 counts. Every slot is written every
// call by its owning block -> no zeroing, no atomics, deterministic.
__device__ float g_part[MAX_M * SPLIT * 16];

__global__ __launch_bounds__(OUT_N)
void velhist_part_kernel(const float* __restrict__ flows,
                         const float* __restrict__ boxes)
{
    __shared__ float2 s_wy[ROWS_PER];   // (wy0, wy1)
    __shared__ int2   s_row[ROWS_PER];  // (r0, r1) as element offsets
    __shared__ float  s_red[7][16];

    const int m = blockIdx.x;
    const int s = blockIdx.y;
    const int j = threadIdx.x;

    const float fb  = boxes[m*5+0];
    const float bx1 = boxes[m*5+1];
    const float by1 = boxes[m*5+2];
    const float bx2 = boxes[m*5+3];
    const float by2 = boxes[m*5+4];
    const int   b   = (int)fb;
    const float roi_w = fmaxf(bx2 - bx1, 1.0f);
    const float roi_h = fmaxf(by2 - by1, 1.0f);

    // Column (x) setup — fully hoisted per thread
    const float gx  = ((float)j + 0.5f) / (float)OUT_N;
    const float px  = bx1 + gx * roi_w;
    const bool  vx  = (px >= -1.0f) && (px <= (float)W);
    const float pxc = fminf(fmaxf(px, 0.0f), (float)(W - 1));
    const float x0f = floorf(pxc);
    const int   x0  = (int)x0f;
    const int   x1i = min(x0 + 1, W - 1);
    const float fx  = pxc - x0f;
    const float wx0 = vx ? (1.0f - fx) : 0.0f;
    const float wx1 = vx ? fx : 0.0f;

    // Row (y) setup for this half's 112 rows
    if (j < ROWS_PER) {
        const int   i   = s * ROWS_PER + j;
        const float gy  = ((float)i + 0.5f) / (float)OUT_N;
        const float py  = by1 + gy * roi_h;
        const bool  vy  = (py >= -1.0f) && (py <= (float)H);
        const float pyc = fminf(fmaxf(py, 0.0f), (float)(H - 1));
        const float y0f = floorf(pyc);
        const int   y0  = (int)y0f;
        const int   y1r = min(y0 + 1, H - 1);
        const float fy  = pyc - y0f;
        s_wy[j]  = make_float2(vy ? (1.0f - fy) : 0.0f, vy ? fy : 0.0f);
        s_row[j] = make_int2(y0 * W, y1r * W);
    }
    __syncthreads();

    const float* __restrict__ pu = flows + (size_t)b * (2 * HW);
    const float* __restrict__ pv = pu + HW;

    float sums[8];
#pragma unroll
    for (int k = 0; k < 8; ++k) sums[k] = 0.0f;
    unsigned long long cnt = 0ULL;   // 8 packed byte counters (max 112 each)

#pragma unroll 2
    for (int i = 0; i < ROWS_PER; ++i) {
        const int2   rr = s_row[i];
        const float2 wy = s_wy[i];
        const float w00 = wy.x * wx0, w01 = wy.x * wx1;
        const float w10 = wy.y * wx0, w11 = wy.y * wx1;

        const float u = pu[rr.x + x0] * w00 + pu[rr.x + x1i] * w01
                      + pu[rr.y + x0] * w10 + pu[rr.y + x1i] * w11;
        const float v = pv[rr.x + x0] * w00 + pv[rr.x + x1i] * w01
                      + pv[rr.y + x0] * w10 + pv[rr.y + x1i] * w11;

        const float sq  = u * u + v * v;
        const float mag = sq * rsqrtf(fmaxf(sq, 1e-38f));  // exact 0 at sq=0

        // bin = floor((atan2(u,v)+pi) * 8/(2pi)); boundaries are the lines
        // u=0, v=0, u=+-v -> exact comparison tree, no atan2.
        int bin;
        if (u < 0.0f) {
            if (v < 0.0f) bin = (u > v)  ? 0 : 1;
            else          bin = (u < -v) ? 2 : 3;
        } else {
            if (v < 0.0f) bin = (u > -v) ? 6 : 7;
            else          bin = (u < v)  ? 4 : 5;
        }
        if (sq == 0.0f) bin = 4;   // atan2(0,0)=0 -> bin 4 (masked samples)

#pragma unroll
        for (int k = 0; k < 8; ++k) sums[k] += (bin == k) ? mag : 0.0f;
        cnt += 1ULL << (bin << 3);
    }

    float cf[8];
#pragma unroll
    for (int k = 0; k < 8; ++k)
        cf[k] = (float)((unsigned)(cnt >> (k << 3)) & 0xFFu);

    // Intra-warp then cross-warp reduction (7 full warps)
#pragma unroll
    for (int off = 16; off > 0; off >>= 1) {
#pragma unroll
        for (int k = 0; k < 8; ++k) {
            sums[k] += __shfl_down_sync(0xFFFFFFFFu, sums[k], off);
            cf[k]   += __shfl_down_sync(0xFFFFFFFFu, cf[k], off);
        }
    }
    const int warp = j >> 5, lane = j & 31;
    if (lane == 0) {
#pragma unroll
        for (int k = 0; k < 8; ++k) {
            s_red[warp][k]     = sums[k];
            s_red[warp][8 + k] = cf[k];
        }
    }
    __syncthreads();
    if (j < 16) {
        float acc = 0.0f;
#pragma unroll
        for (int w = 0; w < 7; ++w) acc += s_red[w][j];
        g_part[((m * SPLIT) + s) * 16 + j] = acc;
    }
}

__global__ void velhist_final_kernel(float* __restrict__ out, int M)
{
    const int t = blockIdx.x * blockDim.x + threadIdx.x;
    if (t >= M * 8) return;
    const int m = t >> 3, k = t & 7;
    float S = 0.0f, C = 0.0f;
#pragma unroll
    for (int s = 0; s < SPLIT; ++s) {
        S += g_part[((m * SPLIT) + s) * 16 + k];
        C += g_part[((m * SPLIT) + s) * 16 + 8 + k];
    }
    out[t] = (C != 0.0f) ? (S / C) : 0.0f;
}

extern "C" void kernel_launch(void* const* d_in, const int* in_sizes, int n_in,
                              void* d_out, int out_size)
{
    const float* flows = (const float*)d_in[0];
    const float* boxes = (const float*)d_in[1];
    float* out = (float*)d_out;
    const int M = in_sizes[1] / 5;

    dim3 grid(M, SPLIT);
    velhist_part_kernel<<<grid, OUT_N>>>(flows, boxes);
    const int tot = M * 8;
    velhist_final_kernel<<<(tot + 255) / 256, 256>>>(out, M);
}

// round 4
// speedup vs baseline: 1.5476x; 1.2576x over previous
#include <cuda_runtime.h>

#define OUT_N 224
#define H 512
#define W 512
#define HW (H*W)
#define SPLIT 4
#define ROWS_PER (OUT_N / SPLIT)   // 56
#define MAX_M 512

// Per-(box, split) partials: 8 sums + 8 counts. Every slot written every
// launch by its owning block before any read -> no init needed.
__device__ float g_part[MAX_M * SPLIT * 16];
// Arrival tickets per box; zero-initialized, reset by the winner each launch.
__device__ int g_tick[MAX_M];

__global__ __launch_bounds__(OUT_N, 8)
void velhist_kernel(const float* __restrict__ flows,
                    const float* __restrict__ boxes,
                    float* __restrict__ out)
{
    __shared__ float2 s_w[ROWS_PER];        // (wy0, wy1) per row
    __shared__ int2   s_r[ROWS_PER + 1];    // (r0, r1) element offsets (+1 for prefetch)
    __shared__ float2 s_hist[8 * OUT_N];    // per-thread (sum, count) per bin
    __shared__ float  s_red[7][16];
    __shared__ int    s_old;

    const int m = blockIdx.x;
    const int s = blockIdx.y;
    const int j = threadIdx.x;

    const float fb  = boxes[m*5+0];
    const float bx1 = boxes[m*5+1];
    const float by1 = boxes[m*5+2];
    const float bx2 = boxes[m*5+3];
    const float by2 = boxes[m*5+4];
    const int   b   = (int)fb;
    const float roi_w = fmaxf(bx2 - bx1, 1.0f);
    const float roi_h = fmaxf(by2 - by1, 1.0f);

    // Column (x) setup — hoisted per thread
    const float gx  = ((float)j + 0.5f) / (float)OUT_N;
    const float px  = bx1 + gx * roi_w;
    const bool  vx  = (px >= -1.0f) && (px <= (float)W);
    const float pxc = fminf(fmaxf(px, 0.0f), (float)(W - 1));
    const float x0f = floorf(pxc);
    const int   x0  = (int)x0f;
    const int   x1i = min(x0 + 1, W - 1);
    const float fx  = pxc - x0f;
    const float wx0 = vx ? (1.0f - fx) : 0.0f;
    const float wx1 = vx ? fx : 0.0f;

    // Zero the histogram (conflict-free: stride 224 ≡ 0 mod 32)
#pragma unroll
    for (int k = 0; k < 8; ++k) s_hist[k * OUT_N + j] = make_float2(0.0f, 0.0f);

    // Row (y) setup: 57 entries (one extra for the prefetch of the last iter)
    if (j <= ROWS_PER) {
        const int   i   = s * ROWS_PER + j;   // may be OUT_N for last split: py stays in-range
        const float gy  = ((float)i + 0.5f) / (float)OUT_N;
        const float py  = by1 + gy * roi_h;
        const bool  vy  = (py >= -1.0f) && (py <= (float)H);
        const float pyc = fminf(fmaxf(py, 0.0f), (float)(H - 1));
        const float y0f = floorf(pyc);
        const int   y0  = (int)y0f;
        const int   y1r = min(y0 + 1, H - 1);
        const float fy  = pyc - y0f;
        if (j < ROWS_PER)
            s_w[j] = make_float2(vy ? (1.0f - fy) : 0.0f, vy ? fy : 0.0f);
        s_r[j] = make_int2(y0 * W, y1r * W);
    }
    __syncthreads();

    const float* __restrict__ pu = flows + (size_t)b * (2 * HW);
    const float* __restrict__ pv = pu + HW;

    // Register tap cache: 8 values for the current (r0, r1) row pair.
    int2 rc = s_r[0];
    float u00 = pu[rc.x + x0], u01 = pu[rc.x + x1i];
    float u10 = pu[rc.y + x0], u11 = pu[rc.y + x1i];
    float v00 = pv[rc.x + x0], v01 = pv[rc.x + x1i];
    float v10 = pv[rc.y + x0], v11 = pv[rc.y + x1i];

    float2* hp = s_hist + j;

    for (int i = 0; i < ROWS_PER; ++i) {
        const float2 wy = s_w[i];
        const float w00 = wy.x * wx0, w01 = wy.x * wx1;
        const float w10 = wy.y * wx0, w11 = wy.y * wx1;

        const float u = u00 * w00 + u01 * w01 + u10 * w10 + u11 * w11;
        const float v = v00 * w00 + v01 * w01 + v10 * w10 + v11 * w11;

        const float sq  = u * u + v * v;
        const float mag = sq * rsqrtf(fmaxf(sq, 1e-38f));   // exact 0 at sq=0

        // bin = floor((atan2(u,v)+pi)*8/(2pi)); boundaries are u=0, v=0, u=+-v
        int bin;
        if (u < 0.0f) {
            if (v < 0.0f) bin = (u > v)  ? 0 : 1;
            else          bin = (u < -v) ? 2 : 3;
        } else {
            if (v < 0.0f) bin = (u > -v) ? 6 : 7;
            else          bin = (u < v)  ? 4 : 5;
        }
        if (sq == 0.0f) bin = 4;   // atan2(0,0)=0 -> bin 4 (masked samples)

        float2 h = hp[bin * OUT_N];
        h.x += mag; h.y += 1.0f;
        hp[bin * OUT_N] = h;

        // Advance the tap cache for the next row (block-uniform branches).
        const int2 rn = s_r[i + 1];
        if (rn.x == rc.y) {                      // advance by exactly one row
            u00 = u10; u01 = u11; v00 = v10; v01 = v11;
            if (rn.y != rc.y) {
                u10 = pu[rn.y + x0]; u11 = pu[rn.y + x1i];
                v10 = pv[rn.y + x0]; v11 = pv[rn.y + x1i];
            }
        } else if (rn.x != rc.x) {               // general jump (safety)
            u00 = pu[rn.x + x0]; u01 = pu[rn.x + x1i];
            u10 = pu[rn.y + x0]; u11 = pu[rn.y + x1i];
            v00 = pv[rn.x + x0]; v01 = pv[rn.x + x1i];
            v10 = pv[rn.y + x0]; v11 = pv[rn.y + x1i];
        } else if (rn.y != rc.y) {               // only lower row changed
            u10 = pu[rn.y + x0]; u11 = pu[rn.y + x1i];
            v10 = pv[rn.y + x0]; v11 = pv[rn.y + x1i];
        }
        rc = rn;
    }
    __syncthreads();

    // Read back this thread's 8 (sum, count) pairs and reduce across the block
    float sm[8], cf[8];
#pragma unroll
    for (int k = 0; k < 8; ++k) {
        const float2 t = s_hist[k * OUT_N + j];
        sm[k] = t.x; cf[k] = t.y;
    }
#pragma unroll
    for (int off = 16; off > 0; off >>= 1) {
#pragma unroll
        for (int k = 0; k < 8; ++k) {
            sm[k] += __shfl_down_sync(0xFFFFFFFFu, sm[k], off);
            cf[k] += __shfl_down_sync(0xFFFFFFFFu, cf[k], off);
        }
    }
    const int warp = j >> 5, lane = j & 31;
    if (lane == 0) {
#pragma unroll
        for (int k = 0; k < 8; ++k) {
            s_red[warp][k]     = sm[k];
            s_red[warp][8 + k] = cf[k];
        }
    }
    __syncthreads();
    if (j < 16) {
        float acc = 0.0f;
#pragma unroll
        for (int w = 0; w < 7; ++w) acc += s_red[w][j];
        g_part[((m * SPLIT) + s) * 16 + j] = acc;
        __threadfence();                 // make partials visible gpu-wide
    }
    __syncthreads();

    // Ticket: the last-arriving block for box m finalizes.
    if (j == 0) s_old = atomicAdd(&g_tick[m], 1);
    __syncthreads();
    if (s_old == SPLIT - 1) {
        __threadfence();                 // acquire: partials of other blocks
        if (j < 8) {
            float S = 0.0f, C = 0.0f;
#pragma unroll
            for (int ss = 0; ss < SPLIT; ++ss) {
                S += g_part[((m * SPLIT) + ss) * 16 + j];
                C += g_part[((m * SPLIT) + ss) * 16 + 8 + j];
            }
            out[m * 8 + j] = (C != 0.0f) ? (S / C) : 0.0f;
        }
        if (j == 0) g_tick[m] = 0;       // reset for the next graph replay
    }
}

extern "C" void kernel_launch(void* const* d_in, const int* in_sizes, int n_in,
                              void* d_out, int out_size)
{
    const float* flows = (const float*)d_in[0];
    const float* boxes = (const float*)d_in[1];
    float* out = (float*)d_out;
    const int M = in_sizes[1] / 5;

    dim3 grid(M, SPLIT);
    velhist_kernel<<<grid, OUT_N>>>(flows, boxes, out);
}

// round 9
// speedup vs baseline: 1.7633x; 1.1394x over previous
#include <cuda_runtime.h>

#define OUT_N 224
#define H 512
#define W 512
#define HW (H*W)
#define SPLIT 4
#define ROWS_PER (OUT_N / SPLIT)   // 56
#define MAX_M 512
#define NWARP 7
#define STAGE_COLS 34

__device__ float g_part[MAX_M * SPLIT * 16];
__device__ int   g_tick[MAX_M];

typedef unsigned long long u64;

__device__ __forceinline__ u64 pk2(float a, float b) {
    u64 r; asm("mov.b64 %0, {%1, %2};" : "=l"(r) : "f"(a), "f"(b)); return r;
}
__device__ __forceinline__ float2 upk2(u64 r) {
    float2 t; asm("mov.b64 {%0, %1}, %2;" : "=f"(t.x), "=f"(t.y) : "l"(r)); return t;
}
__device__ __forceinline__ u64 mul2(u64 a, u64 b) {
    u64 d; asm("mul.rn.f32x2 %0, %1, %2;" : "=l"(d) : "l"(a), "l"(b)); return d;
}
__device__ __forceinline__ u64 fma2(u64 a, u64 b, u64 c) {
    u64 d; asm("fma.rn.f32x2 %0, %1, %2, %3;" : "=l"(d) : "l"(a), "l"(b), "l"(c)); return d;
}

__global__ __launch_bounds__(OUT_N, 8)
void velhist_kernel(const float* __restrict__ flows,
                    const float* __restrict__ boxes,
                    float* __restrict__ out)
{
    __shared__ float2 s_hist[8 * OUT_N];                  // per-thread (sum,count)
    __shared__ float2 s_stage[NWARP][2][STAGE_COLS];      // warp-private row staging
    __shared__ u64    s_wy0p[ROWS_PER], s_wy1p[ROWS_PER]; // packed (wy,wy)
    __shared__ int    s_r0[ROWS_PER + 1], s_r1[ROWS_PER + 1];
    __shared__ int    s_al[ROWS_PER + 1];                 // r1 | (adv<<31)
    __shared__ float  s_red[NWARP][16];
    __shared__ int    s_old;

    const int m = blockIdx.x;
    const int s = blockIdx.y;
    const int j = threadIdx.x;
    const int wid  = j >> 5;
    const int lane = j & 31;

    const float fb  = boxes[m*5+0];
    const float bx1 = boxes[m*5+1];
    const float by1 = boxes[m*5+2];
    const float bx2 = boxes[m*5+3];
    const float by2 = boxes[m*5+4];
    const int   b   = (int)fb;
    const float roi_w = fmaxf(bx2 - bx1, 1.0f);
    const float roi_h = fmaxf(by2 - by1, 1.0f);

    // ---- x (column) setup: fully hoisted per thread ----
    const float gx  = ((float)j + 0.5f) / (float)OUT_N;
    const float px  = bx1 + gx * roi_w;
    const bool  vx  = (px >= -1.0f) && (px <= (float)W);
    const float pxc = fminf(fmaxf(px, 0.0f), (float)(W - 1));
    const float x0f = floorf(pxc);
    const int   x0  = (int)x0f;
    const float fx  = pxc - x0f;
    const float wx0 = vx ? (1.0f - fx) : 0.0f;
    const float wx1 = vx ? fx : 0.0f;
    const u64 wx0p = pk2(wx0, wx0);
    const u64 wx1p = pk2(wx1, wx1);

    // warp-uniform stage base column (x0 monotone within warp -> lane 0 = min)
    const int xb  = __shfl_sync(0xFFFFFFFFu, x0, 0);
    const int col = x0 - xb;                   // 0..31; tap1 at col+1 <= 32
    const int xgA = min(xb + lane, W - 1);     // this lane's staged column
    const int xgB = min(xb + 32 + lane, W - 1);// extra cols 32,33 (lanes 0,1)

    // ---- hist zero (stride 224 float2 -> conflict-free) ----
#pragma unroll
    for (int k = 0; k < 8; ++k) s_hist[k * OUT_N + j] = make_float2(0.0f, 0.0f);

    // ---- y (row) setup ----
    if (j <= ROWS_PER) {
        const int   i   = s * ROWS_PER + j;        // j==ROWS_PER -> harmless extra row
        const float gy  = ((float)i + 0.5f) / (float)OUT_N;
        const float py  = by1 + gy * roi_h;
        const bool  vy  = (py >= -1.0f) && (py <= (float)H);
        const float pyc = fminf(fmaxf(py, 0.0f), (float)(H - 1));
        const float y0f = floorf(pyc);
        const int   y0  = (int)y0f;
        const int   y1r = min(y0 + 1, H - 1);
        const float fy  = pyc - y0f;
        s_r0[j] = y0 * W;
        s_r1[j] = y1r * W;
        if (j < ROWS_PER) {
            const float w0 = vy ? (1.0f - fy) : 0.0f;
            const float w1 = vy ? fy : 0.0f;
            s_wy0p[j] = pk2(w0, w0);
            s_wy1p[j] = pk2(w1, w1);
        }
    }
    __syncthreads();
    if (j >= 1 && j <= ROWS_PER) {
        const int adv = (s_r0[j] != s_r0[j - 1]) ? 1 : 0;
        s_al[j] = s_r1[j] | (adv << 31);
    }
    __syncthreads();

    const float* __restrict__ pu = flows + (size_t)b * (2 * HW);
    const float* __restrict__ pv = pu + HW;

    float2* __restrict__ stg0 = s_stage[wid][0];
    float2* __restrict__ stg1 = s_stage[wid][1];
    const u64* __restrict__ tap0 = (const u64*)stg0 + col;
    const u64* __restrict__ tap1 = (const u64*)stg1 + col;
    float2* __restrict__ hp = s_hist + j;

    // ---- initial rows: r0[0] -> slot0 -> UVx0 ; r1[0] -> slot1 -> UVx1 ----
    u64 uvx0, uvx1;
    {
        const int r0i = s_r0[0];
        stg0[lane] = make_float2(pu[r0i + xgA], pv[r0i + xgA]);
        if (lane < 2) stg0[32 + lane] = make_float2(pu[r0i + xgB], pv[r0i + xgB]);
        __syncwarp();
        uvx0 = fma2(tap0[1], wx1p, mul2(tap0[0], wx0p));
        const int r1i = s_r1[0];
        stg1[lane] = make_float2(pu[r1i + xgA], pv[r1i + xgA]);
        if (lane < 2) stg1[32 + lane] = make_float2(pu[r1i + xgB], pv[r1i + xgB]);
        __syncwarp();
        uvx1 = fma2(tap1[1], wx1p, mul2(tap1[0], wx0p));
    }

    // ---- main loop: straight-line, no data-dependent branches ----
    // Iter i: compute row-pair i from registers, then unconditionally stage
    // row r1[i+1] into slot (i&1) and re-lerp. adv flag via SEL only.
#define ITER(i, STW, TAP) {                                                   \
    const u64 uvp = fma2(uvx1, s_wy1p[i], mul2(uvx0, s_wy0p[i]));             \
    const float2 uv = upk2(uvp);                                              \
    const float u = uv.x, v = uv.y;                                           \
    const float sq  = u * u + v * v;                                          \
    const float mag = sq * rsqrtf(fmaxf(sq, 1e-38f));                         \
    int bin;                                                                  \
    if (u < 0.0f) { if (v < 0.0f) bin = (u > v)  ? 0 : 1;                     \
                    else          bin = (u < -v) ? 2 : 3; }                   \
    else          { if (v < 0.0f) bin = (u > -v) ? 6 : 7;                     \
                    else          bin = (u < v)  ? 4 : 5; }                   \
    if (sq == 0.0f) bin = 4;                                                  \
    float2 h = hp[bin * OUT_N]; h.x += mag; h.y += 1.0f;                      \
    hp[bin * OUT_N] = h;                                                      \
    const int al    = s_al[(i) + 1];                                          \
    const int rload = al & 0x7FFFFFFF;                                        \
    STW[lane] = make_float2(pu[rload + xgA], pv[rload + xgA]);                \
    if (lane < 2) STW[32 + lane] = make_float2(pu[rload + xgB], pv[rload + xgB]); \
    __syncwarp();                                                             \
    const u64 nuv = fma2(TAP[1], wx1p, mul2(TAP[0], wx0p));                   \
    uvx0 = (al < 0) ? uvx1 : uvx0;                                            \
    uvx1 = nuv;                                                               \
}
    for (int i = 0; i < ROWS_PER; i += 2) {
        ITER(i,     stg0, tap0);
        ITER(i + 1, stg1, tap1);
    }
#undef ITER
    __syncthreads();

    // ---- block reduction of the per-thread histograms ----
    float sm[8], cf[8];
#pragma unroll
    for (int k = 0; k < 8; ++k) {
        const float2 t = s_hist[k * OUT_N + j];
        sm[k] = t.x; cf[k] = t.y;
    }
#pragma unroll
    for (int off = 16; off > 0; off >>= 1) {
#pragma unroll
        for (int k = 0; k < 8; ++k) {
            sm[k] += __shfl_down_sync(0xFFFFFFFFu, sm[k], off);
            cf[k] += __shfl_down_sync(0xFFFFFFFFu, cf[k], off);
        }
    }
    if (lane == 0) {
#pragma unroll
        for (int k = 0; k < 8; ++k) {
            s_red[wid][k]     = sm[k];
            s_red[wid][8 + k] = cf[k];
        }
    }
    __syncthreads();
    if (j < 16) {
        float acc = 0.0f;
#pragma unroll
        for (int w = 0; w < NWARP; ++w) acc += s_red[w][j];
        g_part[((m * SPLIT) + s) * 16 + j] = acc;
        __threadfence();
    }
    __syncthreads();

    // ---- last-arriving block for box m finalizes ----
    if (j == 0) s_old = atomicAdd(&g_tick[m], 1);
    __syncthreads();
    if (s_old == SPLIT - 1) {
        __threadfence();
        if (j < 8) {
            float S = 0.0f, C = 0.0f;
#pragma unroll
            for (int ss = 0; ss < SPLIT; ++ss) {
                S += g_part[((m * SPLIT) + ss) * 16 + j];
                C += g_part[((m * SPLIT) + ss) * 16 + 8 + j];
            }
            out[m * 8 + j] = (C != 0.0f) ? (S / C) : 0.0f;
        }
        if (j == 0) g_tick[m] = 0;   // reset for next graph replay
    }
}

extern "C" void kernel_launch(void* const* d_in, const int* in_sizes, int n_in,
                              void* d_out, int out_size)
{
    const float* flows = (const float*)d_in[0];
    const float* boxes = (const float*)d_in[1];
    float* out = (float*)d_out;
    const int M = in_sizes[1] / 5;

    dim3 grid(M, SPLIT);
    velhist_kernel<<<grid, OUT_N>>>(flows, boxes, out);
}

// round 10
// speedup vs baseline: 1.8189x; 1.0315x over previous
#include <cuda_runtime.h>

#define OUT_N 224
#define H 512
#define W 512
#define HW (H*W)
#define SPLIT 4
#define ROWS_PER (OUT_N / SPLIT)   // 56
#define MAX_M 512
#define NWARP 7

__device__ float g_part[MAX_M * SPLIT * 16];
__device__ int   g_tick[MAX_M];

__global__ __launch_bounds__(OUT_N, 8)
void velhist_kernel(const float* __restrict__ flows,
                    const float* __restrict__ boxes,
                    float* __restrict__ out)
{
    __shared__ float4 s_row[ROWS_PER];            // (wy0, wy1, al_bits, pad)
    __shared__ int    s_r0[ROWS_PER + 1], s_r1[ROWS_PER + 1];
    __shared__ float  s_hist[8 * OUT_N];          // per-thread bin sums
    __shared__ float  s_red[NWARP][16];
    __shared__ int    s_old;

    const int m = blockIdx.x;
    const int s = blockIdx.y;
    const int j = threadIdx.x;
    const int wid  = j >> 5;
    const int lane = j & 31;

    const float fb  = boxes[m*5+0];
    const float bx1 = boxes[m*5+1];
    const float by1 = boxes[m*5+2];
    const float bx2 = boxes[m*5+3];
    const float by2 = boxes[m*5+4];
    const int   b   = (int)fb;
    const float roi_w = fmaxf(bx2 - bx1, 1.0f);
    const float roi_h = fmaxf(by2 - by1, 1.0f);

    // ---- x (column) setup: fully hoisted per thread ----
    const float gx  = ((float)j + 0.5f) / (float)OUT_N;
    const float px  = bx1 + gx * roi_w;
    const bool  vx  = (px >= -1.0f) && (px <= (float)W);
    const float pxc = fminf(fmaxf(px, 0.0f), (float)(W - 1));
    const float x0f = floorf(pxc);
    const int   x0  = (int)x0f;
    const int   x1i = min(x0 + 1, W - 1);
    const float fx  = pxc - x0f;
    const float wx0 = vx ? (1.0f - fx) : 0.0f;   // masking folded into weights
    const float wx1 = vx ? fx : 0.0f;

    // ---- hist zero (stride 224 -> conflict-free) ----
#pragma unroll
    for (int k = 0; k < 8; ++k) s_hist[k * OUT_N + j] = 0.0f;

    // ---- y (row) setup ----
    if (j <= ROWS_PER) {
        const int   i   = s * ROWS_PER + j;       // j==ROWS_PER: extra row for prefetch
        const float gy  = ((float)i + 0.5f) / (float)OUT_N;
        const float py  = by1 + gy * roi_h;
        const bool  vy  = (py >= -1.0f) && (py <= (float)H);
        const float pyc = fminf(fmaxf(py, 0.0f), (float)(H - 1));
        const float y0f = floorf(pyc);
        const int   y0  = (int)y0f;
        const int   y1r = min(y0 + 1, H - 1);
        const float fy  = pyc - y0f;
        s_r0[j] = y0 * W;
        s_r1[j] = y1r * W;
        if (j < ROWS_PER) {
            s_row[j].x = vy ? (1.0f - fy) : 0.0f;
            s_row[j].y = vy ? fy : 0.0f;
        }
    }
    __syncthreads();
    if (j < ROWS_PER) {
        const int adv = (s_r0[j + 1] != s_r0[j]) ? 1 : 0;
        s_row[j].z = __int_as_float(s_r1[j + 1] | (adv << 31));
    }
    __syncthreads();

    const float* __restrict__ pu = flows + (size_t)b * (2 * HW);
    const float* __restrict__ pv = pu + HW;

    // ---- register tap cache of x-lerped row values ----
    float ux0, vx0, ux1, vx1;
    float tu0, tu1, tv0, tv1;
    {
        const int r0i = s_r0[0], r1i = s_r1[0];
        const float a0 = pu[r0i + x0], a1 = pu[r0i + x1i];
        const float b0 = pv[r0i + x0], b1 = pv[r0i + x1i];
        ux0 = a0 * wx0 + a1 * wx1;
        vx0 = b0 * wx0 + b1 * wx1;
        tu0 = pu[r1i + x0]; tu1 = pu[r1i + x1i];
        tv0 = pv[r1i + x0]; tv1 = pv[r1i + x1i];
        ux1 = tu0 * wx0 + tu1 * wx1;
        vx1 = tv0 * wx0 + tv1 * wx1;
    }

    unsigned c0 = 0u, c1 = 0u;       // 8 packed byte counters (max 56/bin)
    float* __restrict__ hp = s_hist + j;

    // ---- main loop: branch-free, sync-free, staging-free ----
    // Unconditional reload of row r1[i+1]: when the row pair doesn't advance,
    // r1[i+1]==r1[i] so the loads return identical values (idempotent, L1-hot)
    // and nux/nvx == ux1/vx1 — correctness holds with just 2 SELs on ux0/vx0.
#pragma unroll 4
    for (int i = 0; i < ROWS_PER; ++i) {
        const float4 ri = s_row[i];               // wy0, wy1, al
        const float u = ux0 * ri.x + ux1 * ri.y;
        const float v = vx0 * ri.x + vx1 * ri.y;

        const float sq  = u * u + v * v;
        const float mag = sq * rsqrtf(fmaxf(sq, 1e-38f));   // exact 0 at sq=0

        // bin = floor((atan2(u,v)+pi)*8/(2pi)); boundaries u=0, v=0, u=+-v
        int bin;
        if (u < 0.0f) { bin = (v < 0.0f) ? ((u > v)  ? 0 : 1)
                                         : ((u < -v) ? 2 : 3); }
        else          { bin = (v < 0.0f) ? ((u > -v) ? 6 : 7)
                                         : ((u < v)  ? 4 : 5); }
        if (sq == 0.0f) bin = 4;      // atan2(0,0)=0 -> bin 4 (masked samples)

        hp[bin * OUT_N] += mag;       // LDS.32 + FADD + STS.32, conflict-free
        const unsigned inc = 1u << ((bin & 3) << 3);
        if (bin & 4) c1 += inc; else c0 += inc;    // predicated adds

        const int  al    = __float_as_int(ri.z);
        const int  rload = al & 0x7FFFFFFF;
        tu0 = pu[rload + x0]; tu1 = pu[rload + x1i];
        tv0 = pv[rload + x0]; tv1 = pv[rload + x1i];
        const float nux = tu0 * wx0 + tu1 * wx1;
        const float nvx = tv0 * wx0 + tv1 * wx1;
        const bool adv = (al < 0);
        ux0 = adv ? ux1 : ux0;
        vx0 = adv ? vx1 : vx0;
        ux1 = nux; vx1 = nvx;
    }
    __syncthreads();

    // ---- block reduction ----
    float sm[8], cf[8];
#pragma unroll
    for (int k = 0; k < 4; ++k) {
        cf[k]     = (float)((c0 >> (k << 3)) & 0xFFu);
        cf[4 + k] = (float)((c1 >> (k << 3)) & 0xFFu);
    }
#pragma unroll
    for (int k = 0; k < 8; ++k) sm[k] = s_hist[k * OUT_N + j];

#pragma unroll
    for (int off = 16; off > 0; off >>= 1) {
#pragma unroll
        for (int k = 0; k < 8; ++k) {
            sm[k] += __shfl_down_sync(0xFFFFFFFFu, sm[k], off);
            cf[k] += __shfl_down_sync(0xFFFFFFFFu, cf[k], off);
        }
    }
    if (lane == 0) {
#pragma unroll
        for (int k = 0; k < 8; ++k) {
            s_red[wid][k]     = sm[k];
            s_red[wid][8 + k] = cf[k];
        }
    }
    __syncthreads();
    if (j < 16) {
        float acc = 0.0f;
#pragma unroll
        for (int w = 0; w < NWARP; ++w) acc += s_red[w][j];
        g_part[((m * SPLIT) + s) * 16 + j] = acc;
        __threadfence();
    }
    __syncthreads();

    // ---- last-arriving block for box m finalizes ----
    if (j == 0) s_old = atomicAdd(&g_tick[m], 1);
    __syncthreads();
    if (s_old == SPLIT - 1) {
        __threadfence();
        if (j < 8) {
            float S = 0.0f, C = 0.0f;
#pragma unroll
            for (int ss = 0; ss < SPLIT; ++ss) {
                S += g_part[((m * SPLIT) + ss) * 16 + j];
                C += g_part[((m * SPLIT) + ss) * 16 + 8 + j];
            }
            out[m * 8 + j] = (C != 0.0f) ? (S / C) : 0.0f;
        }
        if (j == 0) g_tick[m] = 0;    // reset for next graph replay
    }
}

extern "C" void kernel_launch(void* const* d_in, const int* in_sizes, int n_in,
                              void* d_out, int out_size)
{
    const float* flows = (const float*)d_in[0];
    const float* boxes = (const float*)d_in[1];
    float* out = (float*)d_out;
    const int M = in_sizes[1] / 5;

    dim3 grid(M, SPLIT);
    velhist_kernel<<<grid, OUT_N>>>(flows, boxes, out);
}